// round 1
// baseline (speedup 1.0000x reference)
#include <cuda_runtime.h>
#include <math.h>

// Problem constants (fixed by the reference)
#define D_MODEL 1024
#define BATCH   4
#define SEQ     2048
#define NHEAD   16
#define HDIM    64
#define MTOT    (BATCH * SEQ)   // 8192

// Scratch buffers (no cudaMalloc allowed) — 4 x 32MB fp32
__device__ float g_Q[MTOT * D_MODEL];
__device__ float g_K[MTOT * D_MODEL];
__device__ float g_V[MTOT * D_MODEL];
__device__ float g_A[MTOT * D_MODEL];

// ---------------------------------------------------------------------------
// SGEMM: C[M,N] = A[M,K] * W[K,N] (+ bias). Row-major everything.
// 128x128 block tile, BK=8, 256 threads, 8x8 per-thread micro-tile.
// M,N,K all multiples of tile sizes here (8192/1024/1024) -> no bounds checks.
// ---------------------------------------------------------------------------
__global__ __launch_bounds__(256) void gemm128(
    const float* __restrict__ A, const float* __restrict__ W,
    const float* __restrict__ bias, float* __restrict__ C,
    int M, int N, int K)
{
    __shared__ float As[8][128];   // transposed A tile: As[k][m]
    __shared__ float Bs[8][128];   // Bs[k][n]

    const int tid = threadIdx.x;
    const int tx = tid & 15;       // 0..15
    const int ty = tid >> 4;       // 0..15
    const int row0 = blockIdx.y * 128;
    const int col0 = blockIdx.x * 128;

    // A-tile load mapping: 128 rows x 8 cols, one float4 per thread
    const int arow = tid >> 1;           // 0..127
    const int acol = (tid & 1) * 4;      // 0 or 4
    // B-tile load mapping: 8 rows x 128 cols, one float4 per thread
    const int brow = tid >> 5;           // 0..7
    const int bcol = (tid & 31) * 4;     // 0..124

    const float* Aptr = A + (size_t)(row0 + arow) * K + acol;
    const float* Wptr = W + (size_t)brow * N + col0 + bcol;

    float acc[8][8];
#pragma unroll
    for (int i = 0; i < 8; i++)
#pragma unroll
        for (int j = 0; j < 8; j++) acc[i][j] = 0.0f;

    for (int k0 = 0; k0 < K; k0 += 8) {
        float4 av = *(const float4*)(Aptr + k0);
        As[acol + 0][arow] = av.x;
        As[acol + 1][arow] = av.y;
        As[acol + 2][arow] = av.z;
        As[acol + 3][arow] = av.w;
        float4 bv = *(const float4*)(Wptr + (size_t)k0 * N);
        *(float4*)&Bs[brow][bcol] = bv;
        __syncthreads();

#pragma unroll
        for (int k = 0; k < 8; k++) {
            float ar[8], br[8];
            *(float4*)(ar)     = *(const float4*)&As[k][ty * 8];
            *(float4*)(ar + 4) = *(const float4*)&As[k][ty * 8 + 4];
            *(float4*)(br)     = *(const float4*)&Bs[k][tx * 8];
            *(float4*)(br + 4) = *(const float4*)&Bs[k][tx * 8 + 4];
#pragma unroll
            for (int i = 0; i < 8; i++)
#pragma unroll
                for (int j = 0; j < 8; j++)
                    acc[i][j] += ar[i] * br[j];
        }
        __syncthreads();
    }

#pragma unroll
    for (int i = 0; i < 8; i++) {
        int r = row0 + ty * 8 + i;
#pragma unroll
        for (int j = 0; j < 8; j += 4) {
            int c = col0 + tx * 8 + j;
            float4 v;
            v.x = acc[i][j + 0]; v.y = acc[i][j + 1];
            v.z = acc[i][j + 2]; v.w = acc[i][j + 3];
            if (bias) {
                v.x += bias[c + 0]; v.y += bias[c + 1];
                v.z += bias[c + 2]; v.w += bias[c + 3];
            }
            *(float4*)&C[(size_t)r * N + c] = v;
        }
    }
}

// ---------------------------------------------------------------------------
// Flash-attention (non-causal). Grid: (B*H, SEQ/64). Block: 256 threads.
// Each block owns 64 query rows of one (b,h); streams K/V in 64-row tiles
// with online softmax. HD = 64. Q pre-scaled by 1/sqrt(D_MODEL).
// ---------------------------------------------------------------------------
#define PAD 68                     // row stride (floats) in smem tiles
#define ATTN_SMEM (4 * 64 * PAD * 4)   // Qs,Ks,Vs,Ss = 69632 bytes

__global__ __launch_bounds__(256) void attn64(
    const float* __restrict__ Q, const float* __restrict__ Kp,
    const float* __restrict__ Vp, float* __restrict__ Out)
{
    extern __shared__ float sm[];
    float* Qs = sm;                 // [64][PAD]
    float* Ks = sm + 64 * PAD;
    float* Vs = sm + 2 * 64 * PAD;
    float* Ss = sm + 3 * 64 * PAD;
    __shared__ float mrow[64], lrow[64], asc[64];

    const int tid = threadIdx.x;
    const int b  = blockIdx.x >> 4;      // / NHEAD
    const int h  = blockIdx.x & 15;      // % NHEAD
    const int q0 = blockIdx.y * 64;
    const float scale = 1.0f / 32.0f;    // 1/sqrt(1024)

    // tile loader mapping: 16 rows per pass x 16 float4-cols
    const int lr = tid >> 4;             // 0..15
    const int lc = (tid & 15) * 4;       // 0..60

    // Load + scale Q tile
#pragma unroll
    for (int p = 0; p < 4; p++) {
        int r = lr + p * 16;
        float4 v = *(const float4*)&Q[(size_t)(b * SEQ + q0 + r) * D_MODEL + h * HDIM + lc];
        v.x *= scale; v.y *= scale; v.z *= scale; v.w *= scale;
        *(float4*)&Qs[r * PAD + lc] = v;
    }
    if (tid < 64) { mrow[tid] = -1e30f; lrow[tid] = 0.0f; }

    // compute mapping: 16x16 thread grid, 4x4 micro-tile
    const int tc = tid & 15;             // col group
    const int tr = tid >> 4;             // row group
    float oacc[4][4];
#pragma unroll
    for (int i = 0; i < 4; i++)
#pragma unroll
        for (int j = 0; j < 4; j++) oacc[i][j] = 0.0f;

    for (int kv0 = 0; kv0 < SEQ; kv0 += 64) {
        __syncthreads();   // previous-iteration consumers done (also covers Q load)
#pragma unroll
        for (int p = 0; p < 4; p++) {
            int r = lr + p * 16;
            size_t gbase = (size_t)(b * SEQ + kv0 + r) * D_MODEL + h * HDIM + lc;
            *(float4*)&Ks[r * PAD + lc] = *(const float4*)&Kp[gbase];
            *(float4*)&Vs[r * PAD + lc] = *(const float4*)&Vp[gbase];
        }
        __syncthreads();

        // S = Qs * Ks^T  (64x64, inner dim 64)
        float s[4][4];
#pragma unroll
        for (int i = 0; i < 4; i++)
#pragma unroll
            for (int j = 0; j < 4; j++) s[i][j] = 0.0f;

#pragma unroll
        for (int d = 0; d < HDIM; d += 4) {
            float4 qv[4], kv[4];
#pragma unroll
            for (int i = 0; i < 4; i++)
                qv[i] = *(const float4*)&Qs[(tr * 4 + i) * PAD + d];
#pragma unroll
            for (int j = 0; j < 4; j++)
                kv[j] = *(const float4*)&Ks[(tc * 4 + j) * PAD + d];
#pragma unroll
            for (int i = 0; i < 4; i++)
#pragma unroll
                for (int j = 0; j < 4; j++)
                    s[i][j] += qv[i].x * kv[j].x + qv[i].y * kv[j].y
                             + qv[i].z * kv[j].z + qv[i].w * kv[j].w;
        }
#pragma unroll
        for (int i = 0; i < 4; i++)
#pragma unroll
            for (int j = 0; j < 4; j++)
                Ss[(tr * 4 + i) * PAD + tc * 4 + j] = s[i][j];
        __syncthreads();

        // Online softmax: one thread per row
        if (tid < 64) {
            int r = tid;
            float m_old = mrow[r];
            float mx = m_old;
#pragma unroll 8
            for (int c = 0; c < 64; c++) mx = fmaxf(mx, Ss[r * PAD + c]);
            float al = __expf(m_old - mx);
            float sum = 0.0f;
#pragma unroll 8
            for (int c = 0; c < 64; c++) {
                float e = __expf(Ss[r * PAD + c] - mx);
                Ss[r * PAD + c] = e;
                sum += e;
            }
            lrow[r] = lrow[r] * al + sum;
            mrow[r] = mx;
            asc[r]  = al;
        }
        __syncthreads();

        // Rescale O, then O += P * V
        float alr[4];
#pragma unroll
        for (int i = 0; i < 4; i++) alr[i] = asc[tr * 4 + i];
#pragma unroll
        for (int i = 0; i < 4; i++)
#pragma unroll
            for (int j = 0; j < 4; j++) oacc[i][j] *= alr[i];

#pragma unroll
        for (int k = 0; k < 64; k += 4) {
            float4 vv0 = *(const float4*)&Vs[(k + 0) * PAD + tc * 4];
            float4 vv1 = *(const float4*)&Vs[(k + 1) * PAD + tc * 4];
            float4 vv2 = *(const float4*)&Vs[(k + 2) * PAD + tc * 4];
            float4 vv3 = *(const float4*)&Vs[(k + 3) * PAD + tc * 4];
#pragma unroll
            for (int i = 0; i < 4; i++) {
                float4 pv = *(const float4*)&Ss[(tr * 4 + i) * PAD + k];
                oacc[i][0] += pv.x * vv0.x + pv.y * vv1.x + pv.z * vv2.x + pv.w * vv3.x;
                oacc[i][1] += pv.x * vv0.y + pv.y * vv1.y + pv.z * vv2.y + pv.w * vv3.y;
                oacc[i][2] += pv.x * vv0.z + pv.y * vv1.z + pv.z * vv2.z + pv.w * vv3.z;
                oacc[i][3] += pv.x * vv0.w + pv.y * vv1.w + pv.z * vv2.w + pv.w * vv3.w;
            }
        }
    }

    // Normalize and write back (head-interleaved [B,S,D] layout)
#pragma unroll
    for (int i = 0; i < 4; i++) {
        int r = tr * 4 + i;
        float inv = 1.0f / lrow[r];
        float4 v;
        v.x = oacc[i][0] * inv; v.y = oacc[i][1] * inv;
        v.z = oacc[i][2] * inv; v.w = oacc[i][3] * inv;
        *(float4*)&Out[(size_t)(b * SEQ + q0 + r) * D_MODEL + h * HDIM + tc * 4] = v;
    }
}

// ---------------------------------------------------------------------------
// Launch
// ---------------------------------------------------------------------------
extern "C" void kernel_launch(void* const* d_in, const int* in_sizes, int n_in,
                              void* d_out, int out_size)
{
    const float* q  = (const float*)d_in[0];
    const float* k  = (const float*)d_in[1];
    const float* v  = (const float*)d_in[2];
    const float* Wq = (const float*)d_in[3];
    const float* Wk = (const float*)d_in[4];
    const float* Wv = (const float*)d_in[5];
    const float* Wo = (const float*)d_in[6];
    const float* bo = (const float*)d_in[7];
    float* out = (float*)d_out;

    float *gq, *gk, *gv, *ga;
    cudaGetSymbolAddress((void**)&gq, g_Q);
    cudaGetSymbolAddress((void**)&gk, g_K);
    cudaGetSymbolAddress((void**)&gv, g_V);
    cudaGetSymbolAddress((void**)&ga, g_A);

    dim3 ggrid(D_MODEL / 128, MTOT / 128);   // (8, 64)

    gemm128<<<ggrid, 256>>>(q, Wq, nullptr, gq, MTOT, D_MODEL, D_MODEL);
    gemm128<<<ggrid, 256>>>(k, Wk, nullptr, gk, MTOT, D_MODEL, D_MODEL);
    gemm128<<<ggrid, 256>>>(v, Wv, nullptr, gv, MTOT, D_MODEL, D_MODEL);

    cudaFuncSetAttribute(attn64, cudaFuncAttributeMaxDynamicSharedMemorySize, ATTN_SMEM);
    attn64<<<dim3(BATCH * NHEAD, SEQ / 64), 256, ATTN_SMEM>>>(gq, gk, gv, ga);

    gemm128<<<ggrid, 256>>>(ga, Wo, bo, out, MTOT, D_MODEL, D_MODEL);
}

// round 3
// speedup vs baseline: 1.4331x; 1.4331x over previous
#include <cuda_runtime.h>
#include <cuda_fp16.h>
#include <math.h>
#include <stdint.h>

// Problem constants
#define D_MODEL 1024
#define BATCH   4
#define SEQ     2048
#define NHEAD   16
#define HDIM    64
#define MTOT    (BATCH * SEQ)   // 8192

// ---------------------------------------------------------------------------
// Scratch (no cudaMalloc allowed)
// ---------------------------------------------------------------------------
__device__ float  g_Q[MTOT * D_MODEL];
__device__ float  g_K[MTOT * D_MODEL];
__device__ float  g_V[MTOT * D_MODEL];
__device__ float  g_A[MTOT * D_MODEL];
__device__ __half h_Qi[MTOT * D_MODEL];
__device__ __half h_Ki[MTOT * D_MODEL];
__device__ __half h_Vi[MTOT * D_MODEL];
__device__ __half h_Ai[MTOT * D_MODEL];
__device__ __half h_Wq[D_MODEL * D_MODEL];   // transposed [N,K]
__device__ __half h_Wk[D_MODEL * D_MODEL];
__device__ __half h_Wv[D_MODEL * D_MODEL];
__device__ __half h_Wo[D_MODEL * D_MODEL];

// ---------------------------------------------------------------------------
// PTX helpers (sm_100-target-safe: ldmatrix / mma.sync / cp.async only)
// ---------------------------------------------------------------------------
__device__ __forceinline__ uint32_t smem_u32(const void* p) {
    uint32_t a;
    asm("{ .reg .u64 t; cvta.to.shared.u64 t, %1; cvt.u32.u64 %0, t; }"
        : "=r"(a) : "l"(p));
    return a;
}

__device__ __forceinline__ void ldm_x4(uint32_t& r0, uint32_t& r1,
                                       uint32_t& r2, uint32_t& r3, uint32_t a) {
    asm volatile("ldmatrix.sync.aligned.m8n8.x4.shared.b16 {%0,%1,%2,%3}, [%4];"
                 : "=r"(r0), "=r"(r1), "=r"(r2), "=r"(r3) : "r"(a));
}

__device__ __forceinline__ void mma16816(float* c, const uint32_t* a,
                                         const uint32_t* b) {
    asm volatile(
        "mma.sync.aligned.m16n8k16.row.col.f32.f16.f16.f32 "
        "{%0,%1,%2,%3}, {%4,%5,%6,%7}, {%8,%9}, {%0,%1,%2,%3};"
        : "+f"(c[0]), "+f"(c[1]), "+f"(c[2]), "+f"(c[3])
        : "r"(a[0]), "r"(a[1]), "r"(a[2]), "r"(a[3]), "r"(b[0]), "r"(b[1]));
}

__device__ __forceinline__ void cp_async16(uint32_t saddr, const void* gaddr) {
    asm volatile("cp.async.cg.shared.global [%0], [%1], 16;"
                 :: "r"(saddr), "l"(gaddr) : "memory");
}
__device__ __forceinline__ void cp_commit() {
    asm volatile("cp.async.commit_group;" ::: "memory");
}
__device__ __forceinline__ void cp_wait0() {
    asm volatile("cp.async.wait_group 0;" ::: "memory");
}

// ---------------------------------------------------------------------------
// fp32 -> fp16 conversion (vectorized, 4 elems/thread)
// ---------------------------------------------------------------------------
__global__ __launch_bounds__(256) void f32_to_f16(const float* __restrict__ in,
                                                  __half* __restrict__ out) {
    int i = (blockIdx.x * 256 + threadIdx.x) * 4;
    float4 v = *(const float4*)(in + i);
    *(__half2*)(out + i)     = __floats2half2_rn(v.x, v.y);
    *(__half2*)(out + i + 2) = __floats2half2_rn(v.z, v.w);
}

// ---------------------------------------------------------------------------
// Weight transpose + convert: Wt[n][k] = (half) W[k][n]   (1024x1024)
// ---------------------------------------------------------------------------
__global__ __launch_bounds__(256) void transpose_w(const float* __restrict__ W,
                                                   __half* __restrict__ Wt) {
    __shared__ float t[32][33];
    int bx = blockIdx.x * 32, by = blockIdx.y * 32;
    int tx = threadIdx.x, ty = threadIdx.y;   // block (32, 8)
#pragma unroll
    for (int i = 0; i < 32; i += 8)
        t[ty + i][tx] = W[(size_t)(by + ty + i) * D_MODEL + bx + tx];
    __syncthreads();
#pragma unroll
    for (int i = 0; i < 32; i += 8)
        Wt[(size_t)(bx + ty + i) * D_MODEL + by + tx] = __float2half_rn(t[tx][ty + i]);
}

// ---------------------------------------------------------------------------
// HMMA fp16 GEMM (fp32 accum): C[M,N] = A[M,K] . Bt[N,K]^T (+bias)
// 128x128 block tile, BK=32, 256 threads (8 warps as 2x4 -> 64x32 warp tile).
// cp.async double-buffered smem. Row pad: 32+8 halves (16B aligned).
// ---------------------------------------------------------------------------
#define LDA 40            // halves per smem row (32 data + 8 pad)
#define BK  32
#define NIT (D_MODEL / BK)   // 32

__global__ __launch_bounds__(256) void gemm_hmma(
    const __half* __restrict__ A, const __half* __restrict__ Bt,
    const float* __restrict__ bias, float* __restrict__ C)
{
    __shared__ __half As[2][128 * LDA];
    __shared__ __half Bs[2][128 * LDA];

    const int tid = threadIdx.x;
    const int wid = tid >> 5, lane = tid & 31;
    const int wm = wid >> 2;            // 0..1  (warp row)
    const int wn = wid & 3;             // 0..3  (warp col)
    const int row0 = blockIdx.y * 128;
    const int col0 = blockIdx.x * 128;

    // cp.async mapping: 512 16B-chunks per tile, 2 per thread.
    // chunk c: row = c>>2, 16B-col = c&3
    const int c0 = tid, c1 = tid + 256;
    const int r0c = c0 >> 2, k0c = (c0 & 3) * 8;   // halves
    const int r1c = c1 >> 2, k1c = (c1 & 3) * 8;
    const __half* gA0 = A + (size_t)(row0 + r0c) * D_MODEL + k0c;
    const __half* gA1 = A + (size_t)(row0 + r1c) * D_MODEL + k1c;
    const __half* gB0 = Bt + (size_t)(col0 + r0c) * D_MODEL + k0c;
    const __half* gB1 = Bt + (size_t)(col0 + r1c) * D_MODEL + k1c;
    uint32_t sA[2], sB[2];
    sA[0] = smem_u32(&As[0][r0c * LDA + k0c]);
    sA[1] = smem_u32(&As[0][r1c * LDA + k1c]);
    sB[0] = smem_u32(&Bs[0][r0c * LDA + k0c]);
    sB[1] = smem_u32(&Bs[0][r1c * LDA + k1c]);
    const uint32_t bufA = (uint32_t)(128 * LDA * 2);   // bytes between buffers
    const uint32_t bufB = bufA;

    // ldmatrix lane addressing
    // A frag (16x16): row = lane&15 within frag, col8 = lane>>4
    const int aRow = lane & 15, aCol8 = (lane >> 4) * 8;
    // B frag (16n x 16k): n = (lane&7) + (lane>>4)*8, k8 = (lane>>3)&1
    const int bN = (lane & 7) + ((lane >> 4) << 3), bK8 = ((lane >> 3) & 1) * 8;

    float acc[4][4][4];
#pragma unroll
    for (int i = 0; i < 4; i++)
#pragma unroll
        for (int j = 0; j < 4; j++)
#pragma unroll
            for (int r = 0; r < 4; r++) acc[i][j][r] = 0.0f;

    // Prologue: load tile 0
    cp_async16(sA[0], gA0); cp_async16(sA[1], gA1);
    cp_async16(sB[0], gB0); cp_async16(sB[1], gB1);
    cp_commit();

    for (int it = 0; it < NIT; it++) {
        cp_wait0();
        __syncthreads();

        if (it + 1 < NIT) {
            const int nb = (it + 1) & 1;
            const int kg = (it + 1) * BK;
            cp_async16(sA[0] + nb * bufA, gA0 + kg);
            cp_async16(sA[1] + nb * bufA, gA1 + kg);
            cp_async16(sB[0] + nb * bufB, gB0 + kg);
            cp_async16(sB[1] + nb * bufB, gB1 + kg);
            cp_commit();
        }

        const __half* at = As[it & 1];
        const __half* bt = Bs[it & 1];

#pragma unroll
        for (int ks = 0; ks < 2; ks++) {
            const int kc = ks * 16;
            uint32_t af[4][4];
#pragma unroll
            for (int mi = 0; mi < 4; mi++) {
                uint32_t addr = smem_u32(at + (wm * 64 + mi * 16 + aRow) * LDA
                                            + kc + aCol8);
                ldm_x4(af[mi][0], af[mi][1], af[mi][2], af[mi][3], addr);
            }
            uint32_t bf[4][2];
#pragma unroll
            for (int ng = 0; ng < 2; ng++) {   // each x4 covers 2 n-frags
                uint32_t addr = smem_u32(bt + (wn * 32 + ng * 16 + bN) * LDA
                                            + kc + bK8);
                ldm_x4(bf[ng * 2][0], bf[ng * 2][1],
                       bf[ng * 2 + 1][0], bf[ng * 2 + 1][1], addr);
            }
#pragma unroll
            for (int mi = 0; mi < 4; mi++)
#pragma unroll
                for (int ni = 0; ni < 4; ni++)
                    mma16816(acc[mi][ni], af[mi], bf[ni]);
        }
        __syncthreads();
    }

    // Epilogue
    const int trow = lane >> 2, tcol = (lane & 3) * 2;
#pragma unroll
    for (int mi = 0; mi < 4; mi++) {
#pragma unroll
        for (int ni = 0; ni < 4; ni++) {
            int gr = row0 + wm * 64 + mi * 16 + trow;
            int gc = col0 + wn * 32 + ni * 8 + tcol;
            float b0 = 0.f, b1 = 0.f;
            if (bias) { b0 = bias[gc]; b1 = bias[gc + 1]; }
            float2 v0 = {acc[mi][ni][0] + b0, acc[mi][ni][1] + b1};
            float2 v1 = {acc[mi][ni][2] + b0, acc[mi][ni][3] + b1};
            *(float2*)&C[(size_t)gr * D_MODEL + gc] = v0;
            *(float2*)&C[(size_t)(gr + 8) * D_MODEL + gc] = v1;
        }
    }
}

// ---------------------------------------------------------------------------
// Flash-attention (unchanged): fp32 SIMT, 64-query tiles
// ---------------------------------------------------------------------------
#define PAD 68
#define ATTN_SMEM (4 * 64 * PAD * 4)

__global__ __launch_bounds__(256) void attn64(
    const float* __restrict__ Q, const float* __restrict__ Kp,
    const float* __restrict__ Vp, float* __restrict__ Out)
{
    extern __shared__ float smf[];
    float* Qs = smf;
    float* Ks = smf + 64 * PAD;
    float* Vs = smf + 2 * 64 * PAD;
    float* Ss = smf + 3 * 64 * PAD;
    __shared__ float mrow[64], lrow[64], asc[64];

    const int tid = threadIdx.x;
    const int b  = blockIdx.x >> 4;
    const int h  = blockIdx.x & 15;
    const int q0 = blockIdx.y * 64;
    const float scale = 1.0f / 32.0f;

    const int lr = tid >> 4;
    const int lc = (tid & 15) * 4;

#pragma unroll
    for (int p = 0; p < 4; p++) {
        int r = lr + p * 16;
        float4 v = *(const float4*)&Q[(size_t)(b * SEQ + q0 + r) * D_MODEL + h * HDIM + lc];
        v.x *= scale; v.y *= scale; v.z *= scale; v.w *= scale;
        *(float4*)&Qs[r * PAD + lc] = v;
    }
    if (tid < 64) { mrow[tid] = -1e30f; lrow[tid] = 0.0f; }

    const int tc = tid & 15;
    const int tr = tid >> 4;
    float oacc[4][4];
#pragma unroll
    for (int i = 0; i < 4; i++)
#pragma unroll
        for (int j = 0; j < 4; j++) oacc[i][j] = 0.0f;

    for (int kv0 = 0; kv0 < SEQ; kv0 += 64) {
        __syncthreads();
#pragma unroll
        for (int p = 0; p < 4; p++) {
            int r = lr + p * 16;
            size_t gbase = (size_t)(b * SEQ + kv0 + r) * D_MODEL + h * HDIM + lc;
            *(float4*)&Ks[r * PAD + lc] = *(const float4*)&Kp[gbase];
            *(float4*)&Vs[r * PAD + lc] = *(const float4*)&Vp[gbase];
        }
        __syncthreads();

        float s[4][4];
#pragma unroll
        for (int i = 0; i < 4; i++)
#pragma unroll
            for (int j = 0; j < 4; j++) s[i][j] = 0.0f;

#pragma unroll
        for (int d = 0; d < HDIM; d += 4) {
            float4 qv[4], kv[4];
#pragma unroll
            for (int i = 0; i < 4; i++)
                qv[i] = *(const float4*)&Qs[(tr * 4 + i) * PAD + d];
#pragma unroll
            for (int j = 0; j < 4; j++)
                kv[j] = *(const float4*)&Ks[(tc * 4 + j) * PAD + d];
#pragma unroll
            for (int i = 0; i < 4; i++)
#pragma unroll
                for (int j = 0; j < 4; j++)
                    s[i][j] += qv[i].x * kv[j].x + qv[i].y * kv[j].y
                             + qv[i].z * kv[j].z + qv[i].w * kv[j].w;
        }
#pragma unroll
        for (int i = 0; i < 4; i++)
#pragma unroll
            for (int j = 0; j < 4; j++)
                Ss[(tr * 4 + i) * PAD + tc * 4 + j] = s[i][j];
        __syncthreads();

        if (tid < 64) {
            int r = tid;
            float m_old = mrow[r];
            float mx = m_old;
#pragma unroll 8
            for (int c = 0; c < 64; c++) mx = fmaxf(mx, Ss[r * PAD + c]);
            float al = __expf(m_old - mx);
            float sum = 0.0f;
#pragma unroll 8
            for (int c = 0; c < 64; c++) {
                float e = __expf(Ss[r * PAD + c] - mx);
                Ss[r * PAD + c] = e;
                sum += e;
            }
            lrow[r] = lrow[r] * al + sum;
            mrow[r] = mx;
            asc[r]  = al;
        }
        __syncthreads();

        float alr[4];
#pragma unroll
        for (int i = 0; i < 4; i++) alr[i] = asc[tr * 4 + i];
#pragma unroll
        for (int i = 0; i < 4; i++)
#pragma unroll
            for (int j = 0; j < 4; j++) oacc[i][j] *= alr[i];

#pragma unroll
        for (int k = 0; k < 64; k += 4) {
            float4 vv0 = *(const float4*)&Vs[(k + 0) * PAD + tc * 4];
            float4 vv1 = *(const float4*)&Vs[(k + 1) * PAD + tc * 4];
            float4 vv2 = *(const float4*)&Vs[(k + 2) * PAD + tc * 4];
            float4 vv3 = *(const float4*)&Vs[(k + 3) * PAD + tc * 4];
#pragma unroll
            for (int i = 0; i < 4; i++) {
                float4 pv = *(const float4*)&Ss[(tr * 4 + i) * PAD + k];
                oacc[i][0] += pv.x * vv0.x + pv.y * vv1.x + pv.z * vv2.x + pv.w * vv3.x;
                oacc[i][1] += pv.x * vv0.y + pv.y * vv1.y + pv.z * vv2.y + pv.w * vv3.y;
                oacc[i][2] += pv.x * vv0.z + pv.y * vv1.z + pv.z * vv2.z + pv.w * vv3.z;
                oacc[i][3] += pv.x * vv0.w + pv.y * vv1.w + pv.z * vv2.w + pv.w * vv3.w;
            }
        }
    }

#pragma unroll
    for (int i = 0; i < 4; i++) {
        int r = tr * 4 + i;
        float inv = 1.0f / lrow[r];
        float4 v;
        v.x = oacc[i][0] * inv; v.y = oacc[i][1] * inv;
        v.z = oacc[i][2] * inv; v.w = oacc[i][3] * inv;
        *(float4*)&Out[(size_t)(b * SEQ + q0 + r) * D_MODEL + h * HDIM + tc * 4] = v;
    }
}

// ---------------------------------------------------------------------------
// Launch
// ---------------------------------------------------------------------------
extern "C" void kernel_launch(void* const* d_in, const int* in_sizes, int n_in,
                              void* d_out, int out_size)
{
    const float* q  = (const float*)d_in[0];
    const float* k  = (const float*)d_in[1];
    const float* v  = (const float*)d_in[2];
    const float* Wq = (const float*)d_in[3];
    const float* Wk = (const float*)d_in[4];
    const float* Wv = (const float*)d_in[5];
    const float* Wo = (const float*)d_in[6];
    const float* bo = (const float*)d_in[7];
    float* out = (float*)d_out;

    float *gq, *gk, *gv, *ga;
    __half *hq, *hk, *hv, *ha, *hwq, *hwk, *hwv, *hwo;
    cudaGetSymbolAddress((void**)&gq, g_Q);
    cudaGetSymbolAddress((void**)&gk, g_K);
    cudaGetSymbolAddress((void**)&gv, g_V);
    cudaGetSymbolAddress((void**)&ga, g_A);
    cudaGetSymbolAddress((void**)&hq, h_Qi);
    cudaGetSymbolAddress((void**)&hk, h_Ki);
    cudaGetSymbolAddress((void**)&hv, h_Vi);
    cudaGetSymbolAddress((void**)&ha, h_Ai);
    cudaGetSymbolAddress((void**)&hwq, h_Wq);
    cudaGetSymbolAddress((void**)&hwk, h_Wk);
    cudaGetSymbolAddress((void**)&hwv, h_Wv);
    cudaGetSymbolAddress((void**)&hwo, h_Wo);

    cudaFuncSetAttribute(attn64, cudaFuncAttributeMaxDynamicSharedMemorySize, ATTN_SMEM);

    const int convBlocks = (MTOT * D_MODEL) / (256 * 4);   // 8192
    f32_to_f16<<<convBlocks, 256>>>(q, hq);
    f32_to_f16<<<convBlocks, 256>>>(k, hk);
    f32_to_f16<<<convBlocks, 256>>>(v, hv);

    dim3 tgrid(32, 32), tblk(32, 8);
    transpose_w<<<tgrid, tblk>>>(Wq, hwq);
    transpose_w<<<tgrid, tblk>>>(Wk, hwk);
    transpose_w<<<tgrid, tblk>>>(Wv, hwv);
    transpose_w<<<tgrid, tblk>>>(Wo, hwo);

    dim3 ggrid(D_MODEL / 128, MTOT / 128);   // (8, 64)
    gemm_hmma<<<ggrid, 256>>>(hq, hwq, nullptr, gq);
    gemm_hmma<<<ggrid, 256>>>(hk, hwk, nullptr, gk);
    gemm_hmma<<<ggrid, 256>>>(hv, hwv, nullptr, gv);

    attn64<<<dim3(BATCH * NHEAD, SEQ / 64), 256, ATTN_SMEM>>>(gq, gk, gv, ga);

    f32_to_f16<<<convBlocks, 256>>>(ga, ha);
    gemm_hmma<<<ggrid, 256>>>(ha, hwo, bo, out);
}

// round 4
// speedup vs baseline: 8.4364x; 5.8866x over previous
#include <cuda_runtime.h>
#include <cuda_fp16.h>
#include <math.h>
#include <stdint.h>

// Problem constants
#define D_MODEL 1024
#define BATCH   4
#define SEQ     2048
#define NHEAD   16
#define HDIM    64
#define MTOT    (BATCH * SEQ)   // 8192

// ---------------------------------------------------------------------------
// Scratch (no cudaMalloc allowed)
// ---------------------------------------------------------------------------
__device__ __half h_Qi[MTOT * D_MODEL];   // fp16 inputs
__device__ __half h_Ki[MTOT * D_MODEL];
__device__ __half h_Vi[MTOT * D_MODEL];
__device__ __half p_Q[MTOT * D_MODEL];    // fp16 projections
__device__ __half p_K[MTOT * D_MODEL];
__device__ __half p_V[MTOT * D_MODEL];
__device__ __half p_A[MTOT * D_MODEL];    // attention output
__device__ __half h_Wq[D_MODEL * D_MODEL];   // transposed weights [N,K]
__device__ __half h_Wk[D_MODEL * D_MODEL];
__device__ __half h_Wv[D_MODEL * D_MODEL];
__device__ __half h_Wo[D_MODEL * D_MODEL];

// ---------------------------------------------------------------------------
// PTX helpers (sm_100 target-safe)
// ---------------------------------------------------------------------------
__device__ __forceinline__ uint32_t smem_u32(const void* p) {
    uint32_t a;
    asm("{ .reg .u64 t; cvta.to.shared.u64 t, %1; cvt.u32.u64 %0, t; }"
        : "=r"(a) : "l"(p));
    return a;
}
__device__ __forceinline__ void ldm_x4(uint32_t& r0, uint32_t& r1,
                                       uint32_t& r2, uint32_t& r3, uint32_t a) {
    asm volatile("ldmatrix.sync.aligned.m8n8.x4.shared.b16 {%0,%1,%2,%3}, [%4];"
                 : "=r"(r0), "=r"(r1), "=r"(r2), "=r"(r3) : "r"(a));
}
__device__ __forceinline__ void ldm_x4t(uint32_t& r0, uint32_t& r1,
                                        uint32_t& r2, uint32_t& r3, uint32_t a) {
    asm volatile("ldmatrix.sync.aligned.m8n8.x4.trans.shared.b16 {%0,%1,%2,%3}, [%4];"
                 : "=r"(r0), "=r"(r1), "=r"(r2), "=r"(r3) : "r"(a));
}
__device__ __forceinline__ void mma16816(float* c, const uint32_t* a,
                                         const uint32_t* b) {
    asm volatile(
        "mma.sync.aligned.m16n8k16.row.col.f32.f16.f16.f32 "
        "{%0,%1,%2,%3}, {%4,%5,%6,%7}, {%8,%9}, {%0,%1,%2,%3};"
        : "+f"(c[0]), "+f"(c[1]), "+f"(c[2]), "+f"(c[3])
        : "r"(a[0]), "r"(a[1]), "r"(a[2]), "r"(a[3]), "r"(b[0]), "r"(b[1]));
}
__device__ __forceinline__ void cp_async16(uint32_t saddr, const void* gaddr) {
    asm volatile("cp.async.cg.shared.global [%0], [%1], 16;"
                 :: "r"(saddr), "l"(gaddr) : "memory");
}
__device__ __forceinline__ void cp_commit() {
    asm volatile("cp.async.commit_group;" ::: "memory");
}
__device__ __forceinline__ uint32_t h2b(float x, float y) {
    __half2 t = __floats2half2_rn(x, y);
    return *(uint32_t*)&t;
}

// ---------------------------------------------------------------------------
// fp32 -> fp16 conversion
// ---------------------------------------------------------------------------
__global__ __launch_bounds__(256) void f32_to_f16(const float* __restrict__ in,
                                                  __half* __restrict__ out) {
    int i = (blockIdx.x * 256 + threadIdx.x) * 4;
    float4 v = *(const float4*)(in + i);
    *(__half2*)(out + i)     = __floats2half2_rn(v.x, v.y);
    *(__half2*)(out + i + 2) = __floats2half2_rn(v.z, v.w);
}

// ---------------------------------------------------------------------------
// Weight transpose + convert: Wt[n][k] = (half) W[k][n]
// ---------------------------------------------------------------------------
__global__ __launch_bounds__(256) void transpose_w(const float* __restrict__ W,
                                                   __half* __restrict__ Wt) {
    __shared__ float t[32][33];
    int bx = blockIdx.x * 32, by = blockIdx.y * 32;
    int tx = threadIdx.x, ty = threadIdx.y;
#pragma unroll
    for (int i = 0; i < 32; i += 8)
        t[ty + i][tx] = W[(size_t)(by + ty + i) * D_MODEL + bx + tx];
    __syncthreads();
#pragma unroll
    for (int i = 0; i < 32; i += 8)
        Wt[(size_t)(bx + ty + i) * D_MODEL + by + tx] = __float2half_rn(t[tx][ty + i]);
}

// ---------------------------------------------------------------------------
// HMMA GEMM: C[M,N] = (A[M,K] . Bt[N,K]^T) * scale (+bias). OutT = half|float
// ---------------------------------------------------------------------------
#define LDA 40
#define BK  32
#define NIT (D_MODEL / BK)   // 32

template <typename OutT>
__global__ __launch_bounds__(256) void gemm_hmma(
    const __half* __restrict__ A, const __half* __restrict__ Bt,
    const float* __restrict__ bias, OutT* __restrict__ C, float scale)
{
    __shared__ __half As[2][128 * LDA];
    __shared__ __half Bs[2][128 * LDA];

    const int tid = threadIdx.x;
    const int wid = tid >> 5, lane = tid & 31;
    const int wm = wid >> 2;
    const int wn = wid & 3;
    const int row0 = blockIdx.y * 128;
    const int col0 = blockIdx.x * 128;

    const int c0 = tid, c1 = tid + 256;
    const int r0c = c0 >> 2, k0c = (c0 & 3) * 8;
    const int r1c = c1 >> 2, k1c = (c1 & 3) * 8;
    const __half* gA0 = A + (size_t)(row0 + r0c) * D_MODEL + k0c;
    const __half* gA1 = A + (size_t)(row0 + r1c) * D_MODEL + k1c;
    const __half* gB0 = Bt + (size_t)(col0 + r0c) * D_MODEL + k0c;
    const __half* gB1 = Bt + (size_t)(col0 + r1c) * D_MODEL + k1c;
    uint32_t sA[2], sB[2];
    sA[0] = smem_u32(&As[0][r0c * LDA + k0c]);
    sA[1] = smem_u32(&As[0][r1c * LDA + k1c]);
    sB[0] = smem_u32(&Bs[0][r0c * LDA + k0c]);
    sB[1] = smem_u32(&Bs[0][r1c * LDA + k1c]);
    const uint32_t bufO = (uint32_t)(128 * LDA * 2);

    const int aRow = lane & 15, aCol8 = (lane >> 4) * 8;
    const int bN = (lane & 7) + ((lane >> 4) << 3), bK8 = ((lane >> 3) & 1) * 8;

    float acc[4][4][4];
#pragma unroll
    for (int i = 0; i < 4; i++)
#pragma unroll
        for (int j = 0; j < 4; j++)
#pragma unroll
            for (int r = 0; r < 4; r++) acc[i][j][r] = 0.0f;

    cp_async16(sA[0], gA0); cp_async16(sA[1], gA1);
    cp_async16(sB[0], gB0); cp_async16(sB[1], gB1);
    cp_commit();

    for (int it = 0; it < NIT; it++) {
        asm volatile("cp.async.wait_group 0;" ::: "memory");
        __syncthreads();

        if (it + 1 < NIT) {
            const int nb = (it + 1) & 1;
            const int kg = (it + 1) * BK;
            cp_async16(sA[0] + nb * bufO, gA0 + kg);
            cp_async16(sA[1] + nb * bufO, gA1 + kg);
            cp_async16(sB[0] + nb * bufO, gB0 + kg);
            cp_async16(sB[1] + nb * bufO, gB1 + kg);
            cp_commit();
        }

        const __half* at = As[it & 1];
        const __half* bt = Bs[it & 1];

#pragma unroll
        for (int ks = 0; ks < 2; ks++) {
            const int kc = ks * 16;
            uint32_t af[4][4];
#pragma unroll
            for (int mi = 0; mi < 4; mi++) {
                uint32_t addr = smem_u32(at + (wm * 64 + mi * 16 + aRow) * LDA
                                            + kc + aCol8);
                ldm_x4(af[mi][0], af[mi][1], af[mi][2], af[mi][3], addr);
            }
            uint32_t bf[4][2];
#pragma unroll
            for (int ng = 0; ng < 2; ng++) {
                uint32_t addr = smem_u32(bt + (wn * 32 + ng * 16 + bN) * LDA
                                            + kc + bK8);
                ldm_x4(bf[ng * 2][0], bf[ng * 2][1],
                       bf[ng * 2 + 1][0], bf[ng * 2 + 1][1], addr);
            }
#pragma unroll
            for (int mi = 0; mi < 4; mi++)
#pragma unroll
                for (int ni = 0; ni < 4; ni++)
                    mma16816(acc[mi][ni], af[mi], bf[ni]);
        }
        __syncthreads();
    }

    const int trow = lane >> 2, tcol = (lane & 3) * 2;
#pragma unroll
    for (int mi = 0; mi < 4; mi++) {
#pragma unroll
        for (int ni = 0; ni < 4; ni++) {
            int gr = row0 + wm * 64 + mi * 16 + trow;
            int gc = col0 + wn * 32 + ni * 8 + tcol;
            float b0 = 0.f, b1 = 0.f;
            if (bias) { b0 = bias[gc]; b1 = bias[gc + 1]; }
            float v00 = acc[mi][ni][0] * scale + b0;
            float v01 = acc[mi][ni][1] * scale + b1;
            float v10 = acc[mi][ni][2] * scale + b0;
            float v11 = acc[mi][ni][3] * scale + b1;
            if (sizeof(OutT) == 2) {
                __half2* p0 = (__half2*)((__half*)C + (size_t)gr * D_MODEL + gc);
                __half2* p1 = (__half2*)((__half*)C + (size_t)(gr + 8) * D_MODEL + gc);
                *p0 = __floats2half2_rn(v00, v01);
                *p1 = __floats2half2_rn(v10, v11);
            } else {
                float2 u0 = {v00, v01}, u1 = {v10, v11};
                *(float2*)((float*)C + (size_t)gr * D_MODEL + gc) = u0;
                *(float2*)((float*)C + (size_t)(gr + 8) * D_MODEL + gc) = u1;
            }
        }
    }
}

// ---------------------------------------------------------------------------
// HMMA flash attention. Grid (B*H, SEQ/128), block 256 (8 warps x 16 q-rows).
// KV chunks of 64, cp.async double-buffered. Q pre-scaled by 1/32 upstream.
// ---------------------------------------------------------------------------
#define AT_LDH  72
#define AT_KBUF (64 * AT_LDH)                 // halves per K/V buffer
#define AT_SMEM ((128 * AT_LDH + 4 * AT_KBUF) * 2)   // 55296 bytes
#define AT_NIT  (SEQ / 64)                    // 32

__global__ __launch_bounds__(256, 2) void attn_hmma(
    const __half* __restrict__ Q, const __half* __restrict__ K,
    const __half* __restrict__ V, __half* __restrict__ O)
{
    extern __shared__ __half sh[];
    __half* Qs = sh;                          // [128][AT_LDH]
    __half* Ks = sh + 128 * AT_LDH;           // 2 buffers [64][AT_LDH]
    __half* Vs = Ks + 2 * AT_KBUF;

    const int tid = threadIdx.x, wid = tid >> 5, lane = tid & 31;
    const int b = blockIdx.x >> 4, h = blockIdx.x & 15;
    const int q0 = blockIdx.y * 128;
    const size_t base = (size_t)b * SEQ * D_MODEL + h * HDIM;

    // Q tile: 128 rows x 64 halves = 1024 x 16B, 4 per thread
#pragma unroll
    for (int j = 0; j < 4; j++) {
        int c = tid + 256 * j;
        int r = c >> 3, c8 = (c & 7) * 8;
        cp_async16(smem_u32(Qs + r * AT_LDH + c8),
                   Q + base + (size_t)(q0 + r) * D_MODEL + c8);
    }
    cp_commit();

    auto loadKV = [&](int it, int buf) {
        int s0 = it * 64;
        __half* kd = Ks + buf * AT_KBUF;
        __half* vd = Vs + buf * AT_KBUF;
#pragma unroll
        for (int j = 0; j < 2; j++) {
            int c = tid + 256 * j;
            int r = c >> 3, c8 = (c & 7) * 8;
            cp_async16(smem_u32(kd + r * AT_LDH + c8),
                       K + base + (size_t)(s0 + r) * D_MODEL + c8);
            cp_async16(smem_u32(vd + r * AT_LDH + c8),
                       V + base + (size_t)(s0 + r) * D_MODEL + c8);
        }
        cp_commit();
    };

    loadKV(0, 0);
    asm volatile("cp.async.wait_group 1;" ::: "memory");
    __syncthreads();

    // Q fragments: m16 x k64 per warp
    uint32_t qf[4][4];
#pragma unroll
    for (int kk = 0; kk < 4; kk++) {
        uint32_t a = smem_u32(Qs + (wid * 16 + (lane & 15)) * AT_LDH
                              + kk * 16 + (lane >> 4) * 8);
        ldm_x4(qf[kk][0], qf[kk][1], qf[kk][2], qf[kk][3], a);
    }

    float m0 = -1e30f, m1 = -1e30f, l0 = 0.f, l1 = 0.f;
    float o[8][4];
#pragma unroll
    for (int nf = 0; nf < 8; nf++)
#pragma unroll
        for (int r = 0; r < 4; r++) o[nf][r] = 0.f;

    for (int it = 0; it < AT_NIT; it++) {
        if (it + 1 < AT_NIT) {
            loadKV(it + 1, (it + 1) & 1);
            asm volatile("cp.async.wait_group 1;" ::: "memory");
        } else {
            asm volatile("cp.async.wait_group 0;" ::: "memory");
        }
        __syncthreads();
        const __half* kd = Ks + (it & 1) * AT_KBUF;
        const __half* vd = Vs + (it & 1) * AT_KBUF;

        // S = Q . K^T : 16 x 64 per warp
        float s[8][4];
#pragma unroll
        for (int nf = 0; nf < 8; nf++)
#pragma unroll
            for (int r = 0; r < 4; r++) s[nf][r] = 0.f;

#pragma unroll
        for (int kk = 0; kk < 4; kk++) {
            uint32_t bk[8][2];
#pragma unroll
            for (int ng = 0; ng < 4; ng++) {
                uint32_t a = smem_u32(kd
                    + (ng * 16 + (lane & 7) + ((lane >> 4) << 3)) * AT_LDH
                    + kk * 16 + ((lane >> 3) & 1) * 8);
                ldm_x4(bk[ng * 2][0], bk[ng * 2][1],
                       bk[ng * 2 + 1][0], bk[ng * 2 + 1][1], a);
            }
#pragma unroll
            for (int nf = 0; nf < 8; nf++)
                mma16816(s[nf], qf[kk], bk[nf]);
        }

        // Online softmax (rows r = lane>>2 and +8)
        float mx0 = -1e30f, mx1 = -1e30f;
#pragma unroll
        for (int nf = 0; nf < 8; nf++) {
            mx0 = fmaxf(mx0, fmaxf(s[nf][0], s[nf][1]));
            mx1 = fmaxf(mx1, fmaxf(s[nf][2], s[nf][3]));
        }
        mx0 = fmaxf(mx0, __shfl_xor_sync(0xffffffffu, mx0, 1));
        mx0 = fmaxf(mx0, __shfl_xor_sync(0xffffffffu, mx0, 2));
        mx1 = fmaxf(mx1, __shfl_xor_sync(0xffffffffu, mx1, 1));
        mx1 = fmaxf(mx1, __shfl_xor_sync(0xffffffffu, mx1, 2));
        float nm0 = fmaxf(m0, mx0), nm1 = fmaxf(m1, mx1);
        float a0 = __expf(m0 - nm0), a1 = __expf(m1 - nm1);
        m0 = nm0; m1 = nm1;

        uint32_t pa[4][4];
        float sum0 = 0.f, sum1 = 0.f;
#pragma unroll
        for (int kk = 0; kk < 4; kk++) {
            float e00 = __expf(s[2 * kk][0] - nm0);
            float e01 = __expf(s[2 * kk][1] - nm0);
            float e02 = __expf(s[2 * kk][2] - nm1);
            float e03 = __expf(s[2 * kk][3] - nm1);
            float e10 = __expf(s[2 * kk + 1][0] - nm0);
            float e11 = __expf(s[2 * kk + 1][1] - nm0);
            float e12 = __expf(s[2 * kk + 1][2] - nm1);
            float e13 = __expf(s[2 * kk + 1][3] - nm1);
            sum0 += e00 + e01 + e10 + e11;
            sum1 += e02 + e03 + e12 + e13;
            pa[kk][0] = h2b(e00, e01);
            pa[kk][1] = h2b(e02, e03);
            pa[kk][2] = h2b(e10, e11);
            pa[kk][3] = h2b(e12, e13);
        }
        sum0 += __shfl_xor_sync(0xffffffffu, sum0, 1);
        sum0 += __shfl_xor_sync(0xffffffffu, sum0, 2);
        sum1 += __shfl_xor_sync(0xffffffffu, sum1, 1);
        sum1 += __shfl_xor_sync(0xffffffffu, sum1, 2);
        l0 = l0 * a0 + sum0;
        l1 = l1 * a1 + sum1;

#pragma unroll
        for (int nf = 0; nf < 8; nf++) {
            o[nf][0] *= a0; o[nf][1] *= a0;
            o[nf][2] *= a1; o[nf][3] *= a1;
        }

        // O += P . V
#pragma unroll
        for (int kk = 0; kk < 4; kk++) {
            uint32_t bv[8][2];
#pragma unroll
            for (int ng = 0; ng < 4; ng++) {
                uint32_t a = smem_u32(vd
                    + (kk * 16 + (lane & 7) + (((lane >> 3) & 1) << 3)) * AT_LDH
                    + ng * 16 + (lane >> 4) * 8);
                ldm_x4t(bv[ng * 2][0], bv[ng * 2][1],
                        bv[ng * 2 + 1][0], bv[ng * 2 + 1][1], a);
            }
#pragma unroll
            for (int nf = 0; nf < 8; nf++)
                mma16816(o[nf], pa[kk], bv[nf]);
        }
        __syncthreads();
    }

    const float inv0 = 1.0f / l0, inv1 = 1.0f / l1;
    const int r0 = q0 + wid * 16 + (lane >> 2);
    const int cb = (lane & 3) * 2;
#pragma unroll
    for (int nf = 0; nf < 8; nf++) {
        size_t i0 = base + (size_t)r0 * D_MODEL + nf * 8 + cb;
        *(__half2*)(O + i0) = __floats2half2_rn(o[nf][0] * inv0, o[nf][1] * inv0);
        *(__half2*)(O + i0 + 8 * D_MODEL) =
            __floats2half2_rn(o[nf][2] * inv1, o[nf][3] * inv1);
    }
}

// ---------------------------------------------------------------------------
// Launch
// ---------------------------------------------------------------------------
extern "C" void kernel_launch(void* const* d_in, const int* in_sizes, int n_in,
                              void* d_out, int out_size)
{
    const float* q  = (const float*)d_in[0];
    const float* k  = (const float*)d_in[1];
    const float* v  = (const float*)d_in[2];
    const float* Wq = (const float*)d_in[3];
    const float* Wk = (const float*)d_in[4];
    const float* Wv = (const float*)d_in[5];
    const float* Wo = (const float*)d_in[6];
    const float* bo = (const float*)d_in[7];
    float* out = (float*)d_out;

    __half *hq, *hk, *hv, *pq, *pk, *pv, *pa;
    __half *hwq, *hwk, *hwv, *hwo;
    cudaGetSymbolAddress((void**)&hq, h_Qi);
    cudaGetSymbolAddress((void**)&hk, h_Ki);
    cudaGetSymbolAddress((void**)&hv, h_Vi);
    cudaGetSymbolAddress((void**)&pq, p_Q);
    cudaGetSymbolAddress((void**)&pk, p_K);
    cudaGetSymbolAddress((void**)&pv, p_V);
    cudaGetSymbolAddress((void**)&pa, p_A);
    cudaGetSymbolAddress((void**)&hwq, h_Wq);
    cudaGetSymbolAddress((void**)&hwk, h_Wk);
    cudaGetSymbolAddress((void**)&hwv, h_Wv);
    cudaGetSymbolAddress((void**)&hwo, h_Wo);

    cudaFuncSetAttribute(attn_hmma, cudaFuncAttributeMaxDynamicSharedMemorySize,
                         AT_SMEM);

    const int convBlocks = (MTOT * D_MODEL) / (256 * 4);
    f32_to_f16<<<convBlocks, 256>>>(q, hq);
    f32_to_f16<<<convBlocks, 256>>>(k, hk);
    f32_to_f16<<<convBlocks, 256>>>(v, hv);

    dim3 tgrid(32, 32), tblk(32, 8);
    transpose_w<<<tgrid, tblk>>>(Wq, hwq);
    transpose_w<<<tgrid, tblk>>>(Wk, hwk);
    transpose_w<<<tgrid, tblk>>>(Wv, hwv);
    transpose_w<<<tgrid, tblk>>>(Wo, hwo);

    dim3 ggrid(D_MODEL / 128, MTOT / 128);
    // Q scaled by 1/sqrt(D_MODEL) = 1/32 in the projection epilogue (exact)
    gemm_hmma<__half><<<ggrid, 256>>>(hq, hwq, nullptr, pq, 1.0f / 32.0f);
    gemm_hmma<__half><<<ggrid, 256>>>(hk, hwk, nullptr, pk, 1.0f);
    gemm_hmma<__half><<<ggrid, 256>>>(hv, hwv, nullptr, pv, 1.0f);

    attn_hmma<<<dim3(BATCH * NHEAD, SEQ / 128), 256, AT_SMEM>>>(pq, pk, pv, pa);

    gemm_hmma<float><<<ggrid, 256>>>(pa, hwo, bo, out, 1.0f);
}

// round 5
// speedup vs baseline: 8.5455x; 1.0129x over previous
#include <cuda_runtime.h>
#include <cuda_fp16.h>
#include <math.h>
#include <stdint.h>

// Problem constants
#define D_MODEL 1024
#define BATCH   4
#define SEQ     2048
#define NHEAD   16
#define HDIM    64
#define MTOT    (BATCH * SEQ)   // 8192

// ---------------------------------------------------------------------------
// Scratch (no cudaMalloc allowed)
// ---------------------------------------------------------------------------
__device__ __half h_Qi[MTOT * D_MODEL];   // fp16 inputs
__device__ __half h_Ki[MTOT * D_MODEL];
__device__ __half h_Vi[MTOT * D_MODEL];
__device__ __half p_Q[MTOT * D_MODEL];    // fp16 projections
__device__ __half p_K[MTOT * D_MODEL];
__device__ __half p_V[MTOT * D_MODEL];
__device__ __half p_A[MTOT * D_MODEL];    // attention output
__device__ __half h_Wq[D_MODEL * D_MODEL];   // transposed weights [N,K]
__device__ __half h_Wk[D_MODEL * D_MODEL];
__device__ __half h_Wv[D_MODEL * D_MODEL];
__device__ __half h_Wo[D_MODEL * D_MODEL];

// ---------------------------------------------------------------------------
// PTX helpers (sm_100 target-safe)
// ---------------------------------------------------------------------------
__device__ __forceinline__ uint32_t smem_u32(const void* p) {
    uint32_t a;
    asm("{ .reg .u64 t; cvta.to.shared.u64 t, %1; cvt.u32.u64 %0, t; }"
        : "=r"(a) : "l"(p));
    return a;
}
__device__ __forceinline__ void ldm_x4(uint32_t& r0, uint32_t& r1,
                                       uint32_t& r2, uint32_t& r3, uint32_t a) {
    asm volatile("ldmatrix.sync.aligned.m8n8.x4.shared.b16 {%0,%1,%2,%3}, [%4];"
                 : "=r"(r0), "=r"(r1), "=r"(r2), "=r"(r3) : "r"(a));
}
__device__ __forceinline__ void ldm_x4t(uint32_t& r0, uint32_t& r1,
                                        uint32_t& r2, uint32_t& r3, uint32_t a) {
    asm volatile("ldmatrix.sync.aligned.m8n8.x4.trans.shared.b16 {%0,%1,%2,%3}, [%4];"
                 : "=r"(r0), "=r"(r1), "=r"(r2), "=r"(r3) : "r"(a));
}
__device__ __forceinline__ void mma16816(float* c, const uint32_t* a,
                                         const uint32_t* b) {
    asm volatile(
        "mma.sync.aligned.m16n8k16.row.col.f32.f16.f16.f32 "
        "{%0,%1,%2,%3}, {%4,%5,%6,%7}, {%8,%9}, {%0,%1,%2,%3};"
        : "+f"(c[0]), "+f"(c[1]), "+f"(c[2]), "+f"(c[3])
        : "r"(a[0]), "r"(a[1]), "r"(a[2]), "r"(a[3]), "r"(b[0]), "r"(b[1]));
}
__device__ __forceinline__ void cp_async16(uint32_t saddr, const void* gaddr) {
    asm volatile("cp.async.cg.shared.global [%0], [%1], 16;"
                 :: "r"(saddr), "l"(gaddr) : "memory");
}
__device__ __forceinline__ void cp_commit() {
    asm volatile("cp.async.commit_group;" ::: "memory");
}
__device__ __forceinline__ void cp_wait1() {
    asm volatile("cp.async.wait_group 1;" ::: "memory");
}
__device__ __forceinline__ uint32_t h2b(float x, float y) {
    __half2 t = __floats2half2_rn(x, y);
    return *(uint32_t*)&t;
}

// ---------------------------------------------------------------------------
// fp32 -> fp16 conversion
// ---------------------------------------------------------------------------
__global__ __launch_bounds__(256) void f32_to_f16(const float* __restrict__ in,
                                                  __half* __restrict__ out) {
    int i = (blockIdx.x * 256 + threadIdx.x) * 4;
    float4 v = *(const float4*)(in + i);
    *(__half2*)(out + i)     = __floats2half2_rn(v.x, v.y);
    *(__half2*)(out + i + 2) = __floats2half2_rn(v.z, v.w);
}

// ---------------------------------------------------------------------------
// Weight transpose + convert: Wt[n][k] = (half) W[k][n]
// ---------------------------------------------------------------------------
__global__ __launch_bounds__(256) void transpose_w(const float* __restrict__ W,
                                                   __half* __restrict__ Wt) {
    __shared__ float t[32][33];
    int bx = blockIdx.x * 32, by = blockIdx.y * 32;
    int tx = threadIdx.x, ty = threadIdx.y;
#pragma unroll
    for (int i = 0; i < 32; i += 8)
        t[ty + i][tx] = W[(size_t)(by + ty + i) * D_MODEL + bx + tx];
    __syncthreads();
#pragma unroll
    for (int i = 0; i < 32; i += 8)
        Wt[(size_t)(bx + ty + i) * D_MODEL + by + tx] = __float2half_rn(t[tx][ty + i]);
}

// ---------------------------------------------------------------------------
// HMMA GEMM: C[M,N] = (A[M,K] . Bt[N,K]^T) * scale (+bias). OutT = half|float
// 3-stage cp.async ring, one __syncthreads per BK iteration.
// ---------------------------------------------------------------------------
#define LDA 40
#define BK  32
#define NIT (D_MODEL / BK)   // 32
#define GS  3
#define GEMM_TILE_H (128 * LDA)                 // halves per tile buffer
#define GEMM_SMEM   (2 * GS * GEMM_TILE_H * 2)  // 61440 bytes

template <typename OutT>
__global__ __launch_bounds__(256) void gemm_hmma(
    const __half* __restrict__ A, const __half* __restrict__ Bt,
    const float* __restrict__ bias, OutT* __restrict__ C, float scale)
{
    extern __shared__ __half gsm[];
    __half* As = gsm;                      // GS buffers
    __half* Bs = gsm + GS * GEMM_TILE_H;   // GS buffers

    const int tid = threadIdx.x;
    const int wid = tid >> 5, lane = tid & 31;
    const int wm = wid >> 2;
    const int wn = wid & 3;
    const int row0 = blockIdx.y * 128;
    const int col0 = blockIdx.x * 128;

    const int c0 = tid, c1 = tid + 256;
    const int r0c = c0 >> 2, k0c = (c0 & 3) * 8;
    const int r1c = c1 >> 2, k1c = (c1 & 3) * 8;
    const __half* gA0 = A + (size_t)(row0 + r0c) * D_MODEL + k0c;
    const __half* gA1 = A + (size_t)(row0 + r1c) * D_MODEL + k1c;
    const __half* gB0 = Bt + (size_t)(col0 + r0c) * D_MODEL + k0c;
    const __half* gB1 = Bt + (size_t)(col0 + r1c) * D_MODEL + k1c;
    uint32_t sA0 = smem_u32(As + r0c * LDA + k0c);
    uint32_t sA1 = smem_u32(As + r1c * LDA + k1c);
    uint32_t sB0 = smem_u32(Bs + r0c * LDA + k0c);
    uint32_t sB1 = smem_u32(Bs + r1c * LDA + k1c);
    const uint32_t bufB = (uint32_t)(GEMM_TILE_H * 2);  // bytes per buffer

    const int aRow = lane & 15, aCol8 = (lane >> 4) * 8;
    const int bN = (lane & 7) + ((lane >> 4) << 3), bK8 = ((lane >> 3) & 1) * 8;

    float acc[4][4][4];
#pragma unroll
    for (int i = 0; i < 4; i++)
#pragma unroll
        for (int j = 0; j < 4; j++)
#pragma unroll
            for (int r = 0; r < 4; r++) acc[i][j][r] = 0.0f;

    // Prologue: tiles 0 and 1 into buffers 0,1
#pragma unroll
    for (int s = 0; s < 2; s++) {
        const int kg = s * BK;
        cp_async16(sA0 + s * bufB, gA0 + kg);
        cp_async16(sA1 + s * bufB, gA1 + kg);
        cp_async16(sB0 + s * bufB, gB0 + kg);
        cp_async16(sB1 + s * bufB, gB1 + kg);
        cp_commit();
    }

    int bufc = 0;   // compute buffer
    int bufn = 2;   // next-load buffer
    for (int it = 0; it < NIT; it++) {
        cp_wait1();          // tile `it` resident (≤1 newest group pending)
        __syncthreads();     // visibility + ring-buffer reuse safety

        const int nt = it + 2;
        if (nt < NIT) {
            const int kg = nt * BK;
            cp_async16(sA0 + bufn * bufB, gA0 + kg);
            cp_async16(sA1 + bufn * bufB, gA1 + kg);
            cp_async16(sB0 + bufn * bufB, gB0 + kg);
            cp_async16(sB1 + bufn * bufB, gB1 + kg);
        }
        cp_commit();         // always commit (keeps group count uniform)
        bufn = (bufn == 2) ? 0 : bufn + 1;

        const __half* at = As + bufc * GEMM_TILE_H;
        const __half* bt = Bs + bufc * GEMM_TILE_H;
        bufc = (bufc == 2) ? 0 : bufc + 1;

#pragma unroll
        for (int ks = 0; ks < 2; ks++) {
            const int kc = ks * 16;
            uint32_t af[4][4];
#pragma unroll
            for (int mi = 0; mi < 4; mi++) {
                uint32_t addr = smem_u32(at + (wm * 64 + mi * 16 + aRow) * LDA
                                            + kc + aCol8);
                ldm_x4(af[mi][0], af[mi][1], af[mi][2], af[mi][3], addr);
            }
            uint32_t bf[4][2];
#pragma unroll
            for (int ng = 0; ng < 2; ng++) {
                uint32_t addr = smem_u32(bt + (wn * 32 + ng * 16 + bN) * LDA
                                            + kc + bK8);
                ldm_x4(bf[ng * 2][0], bf[ng * 2][1],
                       bf[ng * 2 + 1][0], bf[ng * 2 + 1][1], addr);
            }
#pragma unroll
            for (int mi = 0; mi < 4; mi++)
#pragma unroll
                for (int ni = 0; ni < 4; ni++)
                    mma16816(acc[mi][ni], af[mi], bf[ni]);
        }
    }

    const int trow = lane >> 2, tcol = (lane & 3) * 2;
#pragma unroll
    for (int mi = 0; mi < 4; mi++) {
#pragma unroll
        for (int ni = 0; ni < 4; ni++) {
            int gr = row0 + wm * 64 + mi * 16 + trow;
            int gc = col0 + wn * 32 + ni * 8 + tcol;
            float b0 = 0.f, b1 = 0.f;
            if (bias) { b0 = bias[gc]; b1 = bias[gc + 1]; }
            float v00 = acc[mi][ni][0] * scale + b0;
            float v01 = acc[mi][ni][1] * scale + b1;
            float v10 = acc[mi][ni][2] * scale + b0;
            float v11 = acc[mi][ni][3] * scale + b1;
            if (sizeof(OutT) == 2) {
                __half2* q0 = (__half2*)((__half*)C + (size_t)gr * D_MODEL + gc);
                __half2* q1 = (__half2*)((__half*)C + (size_t)(gr + 8) * D_MODEL + gc);
                *q0 = __floats2half2_rn(v00, v01);
                *q1 = __floats2half2_rn(v10, v11);
            } else {
                float2 u0 = {v00, v01}, u1 = {v10, v11};
                *(float2*)((float*)C + (size_t)gr * D_MODEL + gc) = u0;
                *(float2*)((float*)C + (size_t)(gr + 8) * D_MODEL + gc) = u1;
            }
        }
    }
}

// ---------------------------------------------------------------------------
// HMMA flash attention. Grid (B*H, SEQ/128), block 256 (8 warps x 16 q-rows).
// KV chunks of 64, 3-stage cp.async ring, one __syncthreads per KV tile.
// ---------------------------------------------------------------------------
#define AT_LDH  72
#define AT_KBUF (64 * AT_LDH)                         // halves per K/V buffer
#define AT_SMEM ((128 * AT_LDH + 6 * AT_KBUF) * 2)    // 73728 bytes
#define AT_NIT  (SEQ / 64)                            // 32

__global__ __launch_bounds__(256, 2) void attn_hmma(
    const __half* __restrict__ Q, const __half* __restrict__ K,
    const __half* __restrict__ V, __half* __restrict__ O)
{
    extern __shared__ __half sh[];
    __half* Qs = sh;                          // [128][AT_LDH]
    __half* Ks = sh + 128 * AT_LDH;           // 3 buffers [64][AT_LDH]
    __half* Vs = Ks + 3 * AT_KBUF;            // 3 buffers

    const int tid = threadIdx.x, wid = tid >> 5, lane = tid & 31;
    const int b = blockIdx.x >> 4, h = blockIdx.x & 15;
    const int q0 = blockIdx.y * 128;
    const size_t base = (size_t)b * SEQ * D_MODEL + h * HDIM;

    // Q tile: 128 rows x 64 halves, own commit group
#pragma unroll
    for (int j = 0; j < 4; j++) {
        int c = tid + 256 * j;
        int r = c >> 3, c8 = (c & 7) * 8;
        cp_async16(smem_u32(Qs + r * AT_LDH + c8),
                   Q + base + (size_t)(q0 + r) * D_MODEL + c8);
    }
    cp_commit();

    auto issueKV = [&](int it, int buf) {
        int s0 = it * 64;
        __half* kd = Ks + buf * AT_KBUF;
        __half* vd = Vs + buf * AT_KBUF;
#pragma unroll
        for (int j = 0; j < 2; j++) {
            int c = tid + 256 * j;
            int r = c >> 3, c8 = (c & 7) * 8;
            cp_async16(smem_u32(kd + r * AT_LDH + c8),
                       K + base + (size_t)(s0 + r) * D_MODEL + c8);
            cp_async16(smem_u32(vd + r * AT_LDH + c8),
                       V + base + (size_t)(s0 + r) * D_MODEL + c8);
        }
    };

    issueKV(0, 0); cp_commit();
    issueKV(1, 1); cp_commit();

    // Wait for Q (oldest of 3 groups), then build Q fragments
    asm volatile("cp.async.wait_group 2;" ::: "memory");
    __syncthreads();

    uint32_t qf[4][4];
#pragma unroll
    for (int kk = 0; kk < 4; kk++) {
        uint32_t a = smem_u32(Qs + (wid * 16 + (lane & 15)) * AT_LDH
                              + kk * 16 + (lane >> 4) * 8);
        ldm_x4(qf[kk][0], qf[kk][1], qf[kk][2], qf[kk][3], a);
    }

    float m0 = -1e30f, m1 = -1e30f, l0 = 0.f, l1 = 0.f;
    float o[8][4];
#pragma unroll
    for (int nf = 0; nf < 8; nf++)
#pragma unroll
        for (int r = 0; r < 4; r++) o[nf][r] = 0.f;

    int bufc = 0, bufn = 2;
    for (int it = 0; it < AT_NIT; it++) {
        cp_wait1();          // KV tile `it` resident
        __syncthreads();     // visibility + safe ring reuse

        if (it + 2 < AT_NIT) issueKV(it + 2, bufn);
        cp_commit();
        bufn = (bufn == 2) ? 0 : bufn + 1;

        const __half* kd = Ks + bufc * AT_KBUF;
        const __half* vd = Vs + bufc * AT_KBUF;
        bufc = (bufc == 2) ? 0 : bufc + 1;

        // S = Q . K^T : 16 x 64 per warp
        float s[8][4];
#pragma unroll
        for (int nf = 0; nf < 8; nf++)
#pragma unroll
            for (int r = 0; r < 4; r++) s[nf][r] = 0.f;

#pragma unroll
        for (int kk = 0; kk < 4; kk++) {
            uint32_t bk[8][2];
#pragma unroll
            for (int ng = 0; ng < 4; ng++) {
                uint32_t a = smem_u32(kd
                    + (ng * 16 + (lane & 7) + ((lane >> 4) << 3)) * AT_LDH
                    + kk * 16 + ((lane >> 3) & 1) * 8);
                ldm_x4(bk[ng * 2][0], bk[ng * 2][1],
                       bk[ng * 2 + 1][0], bk[ng * 2 + 1][1], a);
            }
#pragma unroll
            for (int nf = 0; nf < 8; nf++)
                mma16816(s[nf], qf[kk], bk[nf]);
        }

        // Online softmax (rows r = lane>>2 and +8)
        float mx0 = -1e30f, mx1 = -1e30f;
#pragma unroll
        for (int nf = 0; nf < 8; nf++) {
            mx0 = fmaxf(mx0, fmaxf(s[nf][0], s[nf][1]));
            mx1 = fmaxf(mx1, fmaxf(s[nf][2], s[nf][3]));
        }
        mx0 = fmaxf(mx0, __shfl_xor_sync(0xffffffffu, mx0, 1));
        mx0 = fmaxf(mx0, __shfl_xor_sync(0xffffffffu, mx0, 2));
        mx1 = fmaxf(mx1, __shfl_xor_sync(0xffffffffu, mx1, 1));
        mx1 = fmaxf(mx1, __shfl_xor_sync(0xffffffffu, mx1, 2));
        float nm0 = fmaxf(m0, mx0), nm1 = fmaxf(m1, mx1);
        float a0 = __expf(m0 - nm0), a1 = __expf(m1 - nm1);
        m0 = nm0; m1 = nm1;

        uint32_t pa[4][4];
        float sum0 = 0.f, sum1 = 0.f;
#pragma unroll
        for (int kk = 0; kk < 4; kk++) {
            float e00 = __expf(s[2 * kk][0] - nm0);
            float e01 = __expf(s[2 * kk][1] - nm0);
            float e02 = __expf(s[2 * kk][2] - nm1);
            float e03 = __expf(s[2 * kk][3] - nm1);
            float e10 = __expf(s[2 * kk + 1][0] - nm0);
            float e11 = __expf(s[2 * kk + 1][1] - nm0);
            float e12 = __expf(s[2 * kk + 1][2] - nm1);
            float e13 = __expf(s[2 * kk + 1][3] - nm1);
            sum0 += e00 + e01 + e10 + e11;
            sum1 += e02 + e03 + e12 + e13;
            pa[kk][0] = h2b(e00, e01);
            pa[kk][1] = h2b(e02, e03);
            pa[kk][2] = h2b(e10, e11);
            pa[kk][3] = h2b(e12, e13);
        }
        sum0 += __shfl_xor_sync(0xffffffffu, sum0, 1);
        sum0 += __shfl_xor_sync(0xffffffffu, sum0, 2);
        sum1 += __shfl_xor_sync(0xffffffffu, sum1, 1);
        sum1 += __shfl_xor_sync(0xffffffffu, sum1, 2);
        l0 = l0 * a0 + sum0;
        l1 = l1 * a1 + sum1;

#pragma unroll
        for (int nf = 0; nf < 8; nf++) {
            o[nf][0] *= a0; o[nf][1] *= a0;
            o[nf][2] *= a1; o[nf][3] *= a1;
        }

        // O += P . V
#pragma unroll
        for (int kk = 0; kk < 4; kk++) {
            uint32_t bv[8][2];
#pragma unroll
            for (int ng = 0; ng < 4; ng++) {
                uint32_t a = smem_u32(vd
                    + (kk * 16 + (lane & 7) + (((lane >> 3) & 1) << 3)) * AT_LDH
                    + ng * 16 + (lane >> 4) * 8);
                ldm_x4t(bv[ng * 2][0], bv[ng * 2][1],
                        bv[ng * 2 + 1][0], bv[ng * 2 + 1][1], a);
            }
#pragma unroll
            for (int nf = 0; nf < 8; nf++)
                mma16816(o[nf], pa[kk], bv[nf]);
        }
    }

    const float inv0 = 1.0f / l0, inv1 = 1.0f / l1;
    const int r0 = q0 + wid * 16 + (lane >> 2);
    const int cb = (lane & 3) * 2;
#pragma unroll
    for (int nf = 0; nf < 8; nf++) {
        size_t i0 = base + (size_t)r0 * D_MODEL + nf * 8 + cb;
        *(__half2*)(O + i0) = __floats2half2_rn(o[nf][0] * inv0, o[nf][1] * inv0);
        *(__half2*)(O + i0 + 8 * D_MODEL) =
            __floats2half2_rn(o[nf][2] * inv1, o[nf][3] * inv1);
    }
}

// ---------------------------------------------------------------------------
// Launch
// ---------------------------------------------------------------------------
extern "C" void kernel_launch(void* const* d_in, const int* in_sizes, int n_in,
                              void* d_out, int out_size)
{
    const float* q  = (const float*)d_in[0];
    const float* k  = (const float*)d_in[1];
    const float* v  = (const float*)d_in[2];
    const float* Wq = (const float*)d_in[3];
    const float* Wk = (const float*)d_in[4];
    const float* Wv = (const float*)d_in[5];
    const float* Wo = (const float*)d_in[6];
    const float* bo = (const float*)d_in[7];
    float* out = (float*)d_out;

    __half *hq, *hk, *hv, *pq, *pk, *pv, *pa;
    __half *hwq, *hwk, *hwv, *hwo;
    cudaGetSymbolAddress((void**)&hq, h_Qi);
    cudaGetSymbolAddress((void**)&hk, h_Ki);
    cudaGetSymbolAddress((void**)&hv, h_Vi);
    cudaGetSymbolAddress((void**)&pq, p_Q);
    cudaGetSymbolAddress((void**)&pk, p_K);
    cudaGetSymbolAddress((void**)&pv, p_V);
    cudaGetSymbolAddress((void**)&pa, p_A);
    cudaGetSymbolAddress((void**)&hwq, h_Wq);
    cudaGetSymbolAddress((void**)&hwk, h_Wk);
    cudaGetSymbolAddress((void**)&hwv, h_Wv);
    cudaGetSymbolAddress((void**)&hwo, h_Wo);

    cudaFuncSetAttribute(attn_hmma, cudaFuncAttributeMaxDynamicSharedMemorySize,
                         AT_SMEM);
    cudaFuncSetAttribute(gemm_hmma<__half>,
                         cudaFuncAttributeMaxDynamicSharedMemorySize, GEMM_SMEM);
    cudaFuncSetAttribute(gemm_hmma<float>,
                         cudaFuncAttributeMaxDynamicSharedMemorySize, GEMM_SMEM);

    const int convBlocks = (MTOT * D_MODEL) / (256 * 4);
    f32_to_f16<<<convBlocks, 256>>>(q, hq);
    f32_to_f16<<<convBlocks, 256>>>(k, hk);
    f32_to_f16<<<convBlocks, 256>>>(v, hv);

    dim3 tgrid(32, 32), tblk(32, 8);
    transpose_w<<<tgrid, tblk>>>(Wq, hwq);
    transpose_w<<<tgrid, tblk>>>(Wk, hwk);
    transpose_w<<<tgrid, tblk>>>(Wv, hwv);
    transpose_w<<<tgrid, tblk>>>(Wo, hwo);

    dim3 ggrid(D_MODEL / 128, MTOT / 128);
    // Q scaled by 1/sqrt(D_MODEL) = 1/32 in the projection epilogue (exact)
    gemm_hmma<__half><<<ggrid, 256, GEMM_SMEM>>>(hq, hwq, nullptr, pq, 1.0f / 32.0f);
    gemm_hmma<__half><<<ggrid, 256, GEMM_SMEM>>>(hk, hwk, nullptr, pk, 1.0f);
    gemm_hmma<__half><<<ggrid, 256, GEMM_SMEM>>>(hv, hwv, nullptr, pv, 1.0f);

    attn_hmma<<<dim3(BATCH * NHEAD, SEQ / 128), 256, AT_SMEM>>>(pq, pk, pv, pa);

    gemm_hmma<float><<<ggrid, 256, GEMM_SMEM>>>(pa, hwo, bo, out, 1.0f);
}